// round 16
// baseline (speedup 1.0000x reference)
#include <cuda_runtime.h>
#include <cuda_bf16.h>
#include <math.h>

// ---------------------------------------------------------------------------
// SeqGraphRepNetwork on GB300 — packed formulation.
// R16 (= R15 resubmit after infra failure): break 1-block/SM barrier
// serialization. LN1 fused into gcn; qkv = 64-row-tile gemm over
// (tiles x 3 projections); tail split into tail1 (out-proj+LN2) and
// tail2 (FFN1+FFN2+pool). All gemm blocks 102KB smem -> 2 blocks/SM.
// ---------------------------------------------------------------------------

#define NMAX   163840
#define LMAX   160
#define BMAXS  1024
#define PA     68            // gemm smem row stride (words)
#define WPC    (128 * PA)    // words per weight plane
#define APC    (64 * PA)     // words per 64-row activation plane
#define QS     20            // attn K smem row stride (words)
#define VS     84            // attn V^T smem row stride (words)

__device__ float d_vsrc[128];
__device__ float d_vdst[128];
__device__ int   d_starts[BMAXS + 1];
__device__ int   d_order[BMAXS];
__device__ unsigned d_wh[6 * WPC];
__device__ unsigned d_wl[6 * WPC];
__device__ float g_buf0[(size_t)NMAX * 128]; // Hu, later ctx
__device__ float g_buf1[(size_t)NMAX * 128]; // Qin
__device__ float g_buf2[(size_t)NMAX * 128]; // q
__device__ float g_buf3[(size_t)NMAX * 128]; // k, later out2
__device__ float g_buf4[(size_t)NMAX * 128]; // v

// ---------------------------------------------------------------------------
__device__ __forceinline__ void bsplit2(float a0, float a1,
                                        unsigned &hi, unsigned &lo)
{
    __nv_bfloat162 h = __float22bfloat162_rn(make_float2(a0, a1));
    float r0 = a0 - __low2float(h);
    float r1 = a1 - __high2float(h);
    __nv_bfloat162 l = __float22bfloat162_rn(make_float2(r0, r1));
    hi = *(unsigned*)&h;
    lo = *(unsigned*)&l;
}

#define MMA_BF16(d0,d1,d2,d3, a0,a1,a2,a3, b0,b1)                         \
    asm volatile("mma.sync.aligned.m16n8k16.row.col.f32.bf16.bf16.f32 "   \
                 "{%0,%1,%2,%3}, {%4,%5,%6,%7}, {%8,%9}, {%0,%1,%2,%3};"  \
                 : "+f"(d0), "+f"(d1), "+f"(d2), "+f"(d3)                 \
                 : "r"(a0), "r"(a1), "r"(a2), "r"(a3), "r"(b0), "r"(b1))

// 64-row x 128-col block mma over K=128. 8 warps (2x4), warp tile 32x32.
__device__ __forceinline__ void mma_block64(
    const unsigned* __restrict__ Ah, const unsigned* __restrict__ Al,
    const unsigned* __restrict__ Bh, const unsigned* __restrict__ Bl,
    float d[2][4][4], int warpRow, int warpCol, int g, int tq)
{
    #pragma unroll
    for (int i = 0; i < 2; ++i)
        #pragma unroll
        for (int j = 0; j < 4; ++j)
            d[i][j][0] = d[i][j][1] = d[i][j][2] = d[i][j][3] = 0.f;

    #pragma unroll
    for (int kk = 0; kk < 8; ++kk) {
        unsigned ah[2][4], al[2][4], bh[4][2], bl[4][2];
        #pragma unroll
        for (int i = 0; i < 2; ++i) {
            int base = (warpRow + i * 16 + g) * PA + kk * 8 + tq;
            ah[i][0] = Ah[base];            ah[i][1] = Ah[base + 8 * PA];
            ah[i][2] = Ah[base + 4];        ah[i][3] = Ah[base + 8 * PA + 4];
            al[i][0] = Al[base];            al[i][1] = Al[base + 8 * PA];
            al[i][2] = Al[base + 4];        al[i][3] = Al[base + 8 * PA + 4];
        }
        #pragma unroll
        for (int j = 0; j < 4; ++j) {
            int base = (warpCol + j * 8 + g) * PA + kk * 8 + tq;
            bh[j][0] = Bh[base];  bh[j][1] = Bh[base + 4];
            bl[j][0] = Bl[base];  bl[j][1] = Bl[base + 4];
        }
        #pragma unroll
        for (int i = 0; i < 2; ++i)
            #pragma unroll
            for (int j = 0; j < 4; ++j) {
                MMA_BF16(d[i][j][0], d[i][j][1], d[i][j][2], d[i][j][3],
                         ah[i][0], ah[i][1], ah[i][2], ah[i][3],
                         bh[j][0], bh[j][1]);
                MMA_BF16(d[i][j][0], d[i][j][1], d[i][j][2], d[i][j][3],
                         ah[i][0], ah[i][1], ah[i][2], ah[i][3],
                         bl[j][0], bl[j][1]);
                MMA_BF16(d[i][j][0], d[i][j][1], d[i][j][2], d[i][j][3],
                         al[i][0], al[i][1], al[i][2], al[i][3],
                         bh[j][0], bh[j][1]);
            }
    }
}

// common 64-row prologue: load+split A rows into planes
__device__ __forceinline__ void load_split64(
    const float* __restrict__ A, int row0, int nrows, int tid,
    unsigned* __restrict__ Ah, unsigned* __restrict__ Al)
{
    for (int i = tid; i < 2048; i += 256) {
        int r = i >> 5, q = i & 31;
        int gr = row0 + r;
        float4 a = (gr < nrows) ? ((const float4*)A)[(size_t)gr * 32 + q]
                                : make_float4(0.f, 0.f, 0.f, 0.f);
        unsigned h0, l0, h1, l1;
        bsplit2(a.x, a.y, h0, l0);
        bsplit2(a.z, a.w, h1, l1);
        Ah[r * PA + 2 * q]     = h0;  Ah[r * PA + 2 * q + 1] = h1;
        Al[r * PA + 2 * q]     = l0;  Al[r * PA + 2 * q + 1] = l1;
    }
}

__device__ __forceinline__ void load_B(
    const unsigned* __restrict__ Wh, const unsigned* __restrict__ Wl,
    int tid, unsigned* __restrict__ Bh, unsigned* __restrict__ Bl)
{
    for (int i = tid; i < 2176; i += 256) {
        ((uint4*)Bh)[i] = ((const uint4*)Wh)[i];
        ((uint4*)Bl)[i] = ((const uint4*)Wl)[i];
    }
}

// ---------------------------------------------------------------------------
// Head: block 0 = scan + length-desc sort; block 1 = prep; 2-7 = wsplit;
// 8-15 = zero pool output.
// ---------------------------------------------------------------------------
__global__ void head_kernel(const int* __restrict__ lengths, int B,
                            const float* __restrict__ attW,
                            const float* __restrict__ a_src,
                            const float* __restrict__ a_dst,
                            const float* __restrict__ in_w,
                            const float* __restrict__ out_w,
                            const float* __restrict__ fw1,
                            const float* __restrict__ fw2,
                            float* __restrict__ outp, int out_n)
{
    __shared__ int s[BMAXS];
    __shared__ int hist[192];
    int blk = blockIdx.x;
    int t = threadIdx.x;
    if (blk == 0) {
        int v = (t < B) ? lengths[t] : 0;
        s[t] = v;
        __syncthreads();
        for (int o = 1; o < BMAXS; o <<= 1) {
            int add = (t >= o) ? s[t - o] : 0;
            __syncthreads();
            s[t] += add;
            __syncthreads();
        }
        if (t < B) d_starts[t] = s[t] - v;
        if (t == B - 1) d_starts[B] = s[t];
        if (t < 192) hist[t] = 0;
        __syncthreads();
        int li = 0;
        if (t < B) {
            li = lengths[t];
            if (li > 191) li = 191;
            if (li < 0) li = 0;
            atomicAdd(&hist[li], 1);
        }
        __syncthreads();
        if (t == 0) {
            int acc = 0;
            for (int L = 191; L >= 0; --L) { int c = hist[L]; hist[L] = acc; acc += c; }
        }
        __syncthreads();
        if (t < B) {
            int pos = atomicAdd(&hist[li], 1);
            d_order[pos] = t;
        }
    } else if (blk == 1) {
        if (t < 128) {
            float vs = 0.f, vd = 0.f;
            #pragma unroll 4
            for (int k = 0; k < 128; ++k) {
                float w = attW[k * 128 + t];
                vs += a_src[k] * w;
                vd += a_dst[k] * w;
            }
            d_vsrc[t] = vs;
            d_vdst[t] = vd;
        }
    } else if (blk < 8) {
        int m = blk - 2;
        const float* src = (m < 3) ? (in_w + m * 16384)
                         : (m == 3 ? out_w : (m == 4 ? fw1 : fw2));
        unsigned* wh = d_wh + m * WPC;
        unsigned* wl = d_wl + m * WPC;
        for (int i = t; i < 4096; i += 1024) {
            int r = i >> 5, q = i & 31;
            float4 w = ((const float4*)src)[i];
            unsigned h0, l0, h1, l1;
            bsplit2(w.x, w.y, h0, l0);
            bsplit2(w.z, w.w, h1, l1);
            wh[r * PA + 2 * q]     = h0;  wh[r * PA + 2 * q + 1] = h1;
            wl[r * PA + 2 * q]     = l0;  wl[r * PA + 2 * q + 1] = l1;
        }
    } else {
        for (int i = (blk - 8) * 1024 + t; i < out_n; i += 8 * 1024)
            outp[i] = 0.f;
    }
}

// ---------------------------------------------------------------------------
// GCN + LN1: warp per node. Writes Hu (g_buf0) and Qin = LN1(Hu) (g_buf1).
// ---------------------------------------------------------------------------
__global__ void gcn_kernel(const float* __restrict__ POI,
                           const float* __restrict__ dde,
                           const int*   __restrict__ sess_idx,
                           const int*   __restrict__ edge_dist,
                           const int*   __restrict__ batch_ids,
                           const int*   __restrict__ node_pos,
                           const int*   __restrict__ lengths,
                           const float* __restrict__ g1,
                           const float* __restrict__ b1v, int N)
{
    int n = blockIdx.x * 8 + (threadIdx.x >> 5);
    if (n >= N) return;
    int lane = threadIdx.x & 31;
    int b = batch_ids[n];
    int p = node_pos[n];
    int l = lengths[b];
    bool h1 = (p > 0);
    bool h2 = (p < l - 1);

    float4 va = ((const float4*)d_vsrc)[lane];
    float4 vb = ((const float4*)d_vdst)[lane];
    float4 xo = ((const float4*)(POI + (size_t)sess_idx[n] * 128))[lane];
    float p1 = xo.x*va.x + xo.y*va.y + xo.z*va.z + xo.w*va.w;
    float p2 = xo.x*vb.x + xo.y*vb.y + xo.z*vb.z + xo.w*vb.w;
    float qq = 0.f;
    if (h1) {
        float4 xe = ((const float4*)(dde + (size_t)edge_dist[n - 1 - b] * 128))[lane];
        qq = xe.x*va.x + xe.y*va.y + xe.z*va.z + xe.w*va.w;
    }
    #pragma unroll
    for (int o = 16; o; o >>= 1) {
        p1 += __shfl_xor_sync(0xffffffffu, p1, o);
        p2 += __shfl_xor_sync(0xffffffffu, p2, o);
        qq += __shfl_xor_sync(0xffffffffu, qq, o);
    }

    float L1 = h1 ? (p1 + qq) : -1e30f;
    float L2 = h2 ? p2 : -1e30f;
    float m  = fmaxf(L1, L2);
    float e1 = h1 ? expf(L1 - m) : 0.f;
    float e2 = h2 ? expf(L2 - m) : 0.f;
    float inv = 1.f / (e1 + e2 + 1e-16f);
    float a1 = e1 * inv, a2 = e2 * inv;

    float4 hu = make_float4(0.f, 0.f, 0.f, 0.f);
    if (h1) {
        float4 x = ((const float4*)(POI + (size_t)sess_idx[n - 1] * 128))[lane];
        hu.x += a1 * x.x; hu.y += a1 * x.y; hu.z += a1 * x.z; hu.w += a1 * x.w;
    }
    if (h2) {
        float4 x = ((const float4*)(POI + (size_t)sess_idx[n + 1] * 128))[lane];
        hu.x += a2 * x.x; hu.y += a2 * x.y; hu.z += a2 * x.z; hu.w += a2 * x.w;
    }
    ((float4*)g_buf0)[(size_t)n * 32 + lane] = hu;

    float s1 = hu.x + hu.y + hu.z + hu.w;
    float s2 = hu.x*hu.x + hu.y*hu.y + hu.z*hu.z + hu.w*hu.w;
    #pragma unroll
    for (int o = 16; o; o >>= 1) {
        s1 += __shfl_xor_sync(0xffffffffu, s1, o);
        s2 += __shfl_xor_sync(0xffffffffu, s2, o);
    }
    float mu   = s1 * (1.f / 128.f);
    float var  = fmaxf(s2 * (1.f / 128.f) - mu * mu, 0.f);
    float rstd = rsqrtf(var + 1e-8f);
    float4 gg = ((const float4*)g1)[lane];
    float4 bb = ((const float4*)b1v)[lane];
    float4 o4;
    o4.x = (hu.x - mu) * rstd * gg.x + bb.x;
    o4.y = (hu.y - mu) * rstd * gg.y + bb.y;
    o4.z = (hu.z - mu) * rstd * gg.z + bb.z;
    o4.w = (hu.w - mu) * rstd * gg.w + bb.w;
    ((float4*)g_buf1)[(size_t)n * 32 + lane] = o4;
}

// ---------------------------------------------------------------------------
// QKV: one 64-row gemm per block; blockIdx.y selects projection (0=q from
// Qin, 1=k from Hu, 2=v from Hu). 256 threads, 2 blocks/SM.
// ---------------------------------------------------------------------------
__global__ void __launch_bounds__(256, 2)
qkv_kernel(const float* __restrict__ Hu, const float* __restrict__ Qin,
           const unsigned* __restrict__ Wh3, const unsigned* __restrict__ Wl3,
           const float* __restrict__ in_b,
           float* __restrict__ qout, float* __restrict__ kout,
           float* __restrict__ vout, int nrows)
{
    extern __shared__ unsigned smu[];
    unsigned* Ah = smu;                // [64][PA]
    unsigned* Al = Ah + APC;
    unsigned* Bh = Al + APC;           // [128][PA]
    unsigned* Bl = Bh + WPC;
    int tid  = threadIdx.x;
    int row0 = blockIdx.x * 64;
    int s    = blockIdx.y;
    int lane = tid & 31, wid = tid >> 5;
    int g  = lane >> 2, tq = lane & 3;
    int warpRow = (wid & 1) * 32;
    int warpCol = (wid >> 1) * 32;

    const float* A = (s == 0) ? Qin : Hu;
    load_split64(A, row0, nrows, tid, Ah, Al);
    load_B(Wh3 + s * WPC, Wl3 + s * WPC, tid, Bh, Bl);
    __syncthreads();

    float d[2][4][4];
    mma_block64(Ah, Al, Bh, Bl, d, warpRow, warpCol, g, tq);

    float* op = (s == 0) ? qout : ((s == 1) ? kout : vout);
    const float* bias = in_b + s * 128;
    #pragma unroll
    for (int j = 0; j < 4; ++j) {
        int c0 = warpCol + j * 8 + tq * 2;
        float bj0 = bias[c0], bj1 = bias[c0 + 1];
        #pragma unroll
        for (int i = 0; i < 2; ++i) {
            int gr = row0 + warpRow + i * 16 + g;
            if (gr < nrows)
                *(float2*)(op + (size_t)gr * 128 + c0) =
                    make_float2(d[i][j][0] + bj0, d[i][j][1] + bj1);
            if (gr + 8 < nrows)
                *(float2*)(op + (size_t)(gr + 8) * 128 + c0) =
                    make_float2(d[i][j][2] + bj0, d[i][j][3] + bj1);
        }
    }
}

// ---------------------------------------------------------------------------
// tail1: out2 = LN2(ctx @ Wo^T + bo + Qin) -> gmem. 64-row tile.
// ---------------------------------------------------------------------------
__global__ void __launch_bounds__(256, 2)
tail1_kernel(const float* __restrict__ ctx, const float* __restrict__ Qin,
             const unsigned* __restrict__ Wh, const unsigned* __restrict__ Wl,
             const float* __restrict__ out_b,
             const float* __restrict__ lng, const float* __restrict__ lnb,
             float* __restrict__ out2, int nrows)
{
    extern __shared__ unsigned smu[];
    unsigned* Ah = smu;
    unsigned* Al = Ah + APC;
    unsigned* Bh = Al + APC;
    unsigned* Bl = Bh + WPC;
    float*    O  = (float*)Bh;         // [64][132] staging after mma
    int tid  = threadIdx.x;
    int row0 = blockIdx.x * 64;
    int lane = tid & 31, wid = tid >> 5;
    int g  = lane >> 2, tq = lane & 3;
    int warpRow = (wid & 1) * 32;
    int warpCol = (wid >> 1) * 32;

    load_split64(ctx, row0, nrows, tid, Ah, Al);
    load_B(Wh, Wl, tid, Bh, Bl);
    __syncthreads();

    float d[2][4][4];
    mma_block64(Ah, Al, Bh, Bl, d, warpRow, warpCol, g, tq);
    __syncthreads();   // everyone done with B before staging overwrites it

    #pragma unroll
    for (int i = 0; i < 2; ++i) {
        int r0 = warpRow + i * 16 + g;
        #pragma unroll
        for (int j = 0; j < 4; ++j) {
            int c0 = warpCol + j * 8 + tq * 2;
            *(float2*)&O[r0 * 132 + c0]       = make_float2(d[i][j][0], d[i][j][1]);
            *(float2*)&O[(r0 + 8) * 132 + c0] = make_float2(d[i][j][2], d[i][j][3]);
        }
    }
    __syncthreads();

    float4 bo = ((const float4*)out_b)[lane];
    float4 gg = ((const float4*)lng)[lane];
    float4 be = ((const float4*)lnb)[lane];
    for (int r = wid; r < 64; r += 8) {
        int gr = row0 + r;
        if (gr >= nrows) continue;
        float4 v = *(float4*)&O[r * 132 + lane * 4];
        float4 qv = ((const float4*)(Qin + (size_t)gr * 128))[lane];
        v.x += bo.x + qv.x; v.y += bo.y + qv.y;
        v.z += bo.z + qv.z; v.w += bo.w + qv.w;
        float s1 = v.x + v.y + v.z + v.w;
        float s2 = v.x*v.x + v.y*v.y + v.z*v.z + v.w*v.w;
        #pragma unroll
        for (int o = 16; o; o >>= 1) {
            s1 += __shfl_xor_sync(0xffffffffu, s1, o);
            s2 += __shfl_xor_sync(0xffffffffu, s2, o);
        }
        float mu   = s1 * (1.f / 128.f);
        float var  = fmaxf(s2 * (1.f / 128.f) - mu * mu, 0.f);
        float rstd = rsqrtf(var + 1e-8f);
        v.x = (v.x - mu) * rstd * gg.x + be.x;
        v.y = (v.y - mu) * rstd * gg.y + be.y;
        v.z = (v.z - mu) * rstd * gg.z + be.z;
        v.w = (v.w - mu) * rstd * gg.w + be.w;
        ((float4*)(out2 + (size_t)gr * 128))[lane] = v;
    }
}

// ---------------------------------------------------------------------------
// tail2: h = relu(out2@W1^T + b1) (in smem); out3 = h@W2^T + b2 + out2;
// pool: S_u += out3 / l.  64-row tile.
// ---------------------------------------------------------------------------
__global__ void __launch_bounds__(256, 2)
tail2_kernel(const float* __restrict__ out2,
             const unsigned* __restrict__ Wh, const unsigned* __restrict__ Wl,
             const float* __restrict__ fb1, const float* __restrict__ fb2,
             const int* __restrict__ batch_ids, const int* __restrict__ lengths,
             float* __restrict__ pool_out, int nrows)
{
    extern __shared__ unsigned smu[];
    unsigned* Ah = smu;
    unsigned* Al = Ah + APC;
    unsigned* Bh = Al + APC;
    unsigned* Bl = Bh + WPC;
    int tid  = threadIdx.x;
    int row0 = blockIdx.x * 64;
    int lane = tid & 31, wid = tid >> 5;
    int g  = lane >> 2, tq = lane & 3;
    int warpRow = (wid & 1) * 32;
    int warpCol = (wid >> 1) * 32;

    load_split64(out2, row0, nrows, tid, Ah, Al);
    load_B(Wh, Wl, tid, Bh, Bl);          // W1
    __syncthreads();

    float d[2][4][4];
    mma_block64(Ah, Al, Bh, Bl, d, warpRow, warpCol, g, tq);
    __syncthreads();   // done reading A(out2 planes) and B(W1)

    // h = relu(d + b1) -> back into A planes (owned cells)
    #pragma unroll
    for (int i = 0; i < 2; ++i) {
        #pragma unroll
        for (int j = 0; j < 4; ++j) {
            int c0 = warpCol + j * 8 + tq * 2;
            float bx = fb1[c0], by = fb1[c0 + 1];
            int r0 = warpRow + i * 16 + g;
            float v0 = fmaxf(d[i][j][0] + bx, 0.f);
            float v1 = fmaxf(d[i][j][1] + by, 0.f);
            float v2 = fmaxf(d[i][j][2] + bx, 0.f);
            float v3 = fmaxf(d[i][j][3] + by, 0.f);
            unsigned h0, l0, h1, l1;
            bsplit2(v0, v1, h0, l0);
            bsplit2(v2, v3, h1, l1);
            int w0 = r0 * PA + (c0 >> 1);
            int w1 = (r0 + 8) * PA + (c0 >> 1);
            Ah[w0] = h0;  Al[w0] = l0;
            Ah[w1] = h1;  Al[w1] = l1;
        }
    }
    load_B(Wh + WPC, Wl + WPC, tid, Bh, Bl);  // W2
    __syncthreads();

    mma_block64(Ah, Al, Bh, Bl, d, warpRow, warpCol, g, tq);

    #pragma unroll
    for (int i = 0; i < 2; ++i) {
        #pragma unroll
        for (int half = 0; half < 2; ++half) {
            int r0 = warpRow + i * 16 + g + half * 8;
            int gr = row0 + r0;
            if (gr >= nrows) continue;
            int bsess = batch_ids[gr];
            float invl = 1.f / (float)lengths[bsess];
            float* outrow = pool_out + (size_t)bsess * 128;
            const float* o2row = out2 + (size_t)gr * 128;
            #pragma unroll
            for (int j = 0; j < 4; ++j) {
                int c0 = warpCol + j * 8 + tq * 2;
                float2 o2 = *(const float2*)(o2row + c0);
                float v0 = d[i][j][2 * half]     + fb2[c0]     + o2.x;
                float v1 = d[i][j][2 * half + 1] + fb2[c0 + 1] + o2.y;
                atomicAdd(outrow + c0,     v0 * invl);
                atomicAdd(outrow + c0 + 1, v1 * invl);
            }
        }
    }
}

// ---------------------------------------------------------------------------
// Tensor-core attention (unchanged).
// ---------------------------------------------------------------------------
__global__ void __launch_bounds__(256, 3)
attn_mma_kernel(const float* __restrict__ qp, const float* __restrict__ kp,
                const float* __restrict__ vp, float* __restrict__ ctx,
                const int* __restrict__ lengths)
{
    int b = d_order[blockIdx.x];
    int h = blockIdx.y;
    int n0 = d_starts[b];
    int l  = lengths[b];
    extern __shared__ unsigned sm[];
    unsigned* Kh = sm;                   // [160][QS]
    unsigned* Kl = Kh + 160 * QS;
    unsigned* Vh = Kl + 160 * QS;        // [32][VS]
    unsigned* Vl = Vh + 32 * VS;
    int tid = threadIdx.x;
    int hc  = h * 32;

    for (int i = tid; i < l * 16; i += 256) {
        int s = i >> 4, cp = i & 15;
        size_t gi = (((size_t)(n0 + s) * 128 + hc) >> 1) + cp;
        float2 kv = ((const float2*)kp)[gi];
        unsigned hi, lo;
        bsplit2(kv.x, kv.y, hi, lo);
        Kh[s * QS + cp] = hi; Kl[s * QS + cp] = lo;
    }
    int njp = (l + 1) >> 1;
    for (int i = tid; i < njp * 32; i += 256) {
        int jp = i >> 5, d = i & 31;
        int j0 = 2 * jp;
        float v0 = vp[(size_t)(n0 + j0) * 128 + hc + d];
        float v1 = (j0 + 1 < l) ? vp[(size_t)(n0 + j0 + 1) * 128 + hc + d] : 0.f;
        unsigned hi, lo;
        bsplit2(v0, v1, hi, lo);
        Vh[d * VS + jp] = hi; Vl[d * VS + jp] = lo;
    }
    int nchunks = (l + 31) >> 5;
    int jmax = nchunks * 16;
    for (int i = tid; i < (jmax - njp) * 32; i += 256) {
        int d = i & 31, jp = njp + (i >> 5);
        Vh[d * VS + jp] = 0u;
        Vl[d * VS + jp] = 0u;
    }
    __syncthreads();

    int lane = tid & 31, wid = tid >> 5;
    int g = lane >> 2, tq = lane & 3;
    int nrt = (l + 15) >> 4;
    const float scale = 0.17677669529663687f;

    for (int rt = wid; rt < nrt; rt += 8) {
        int i0 = rt * 16;
        unsigned qah[2][4], qal[2][4];
        {
            const float2* qr0 = (const float2*)(qp + (size_t)(n0 + i0 + g) * 128 + hc);
            const float2* qr1 = (const float2*)(qp + (size_t)(n0 + i0 + 8 + g) * 128 + hc);
            #pragma unroll
            for (int kk = 0; kk < 2; ++kk) {
                float2 v;
                v = qr0[kk * 8 + tq];     bsplit2(v.x, v.y, qah[kk][0], qal[kk][0]);
                v = qr1[kk * 8 + tq];     bsplit2(v.x, v.y, qah[kk][1], qal[kk][1]);
                v = qr0[kk * 8 + tq + 4]; bsplit2(v.x, v.y, qah[kk][2], qal[kk][2]);
                v = qr1[kk * 8 + tq + 4]; bsplit2(v.x, v.y, qah[kk][3], qal[kk][3]);
            }
        }

        float ca[4][4];
        #pragma unroll
        for (int nt = 0; nt < 4; ++nt)
            ca[nt][0] = ca[nt][1] = ca[nt][2] = ca[nt][3] = 0.f;
        float m0 = -1e30f, m1 = -1e30f;
        float sum0 = 0.f, sum1 = 0.f;

        for (int ch = 0; ch < nchunks; ++ch) {
            float sa[4][4];
            #pragma unroll
            for (int ct = 0; ct < 4; ++ct)
                sa[ct][0] = sa[ct][1] = sa[ct][2] = sa[ct][3] = 0.f;

            #pragma unroll
            for (int ct = 0; ct < 4; ++ct) {
                #pragma unroll
                for (int kk = 0; kk < 2; ++kk) {
                    int base = ((ch * 4 + ct) * 8 + g) * QS + kk * 8 + tq;
                    unsigned bh0 = Kh[base], bh1 = Kh[base + 4];
                    unsigned bl0 = Kl[base], bl1 = Kl[base + 4];
                    MMA_BF16(sa[ct][0], sa[ct][1], sa[ct][2], sa[ct][3],
                             qah[kk][0], qah[kk][1], qah[kk][2], qah[kk][3], bh0, bh1);
                    MMA_BF16(sa[ct][0], sa[ct][1], sa[ct][2], sa[ct][3],
                             qah[kk][0], qah[kk][1], qah[kk][2], qah[kk][3], bl0, bl1);
                    MMA_BF16(sa[ct][0], sa[ct][1], sa[ct][2], sa[ct][3],
                             qal[kk][0], qal[kk][1], qal[kk][2], qal[kk][3], bh0, bh1);
                }
            }

            bool full = ((ch + 1) << 5) <= l;
            float cm0 = -1e30f, cm1 = -1e30f;
            if (full) {
                #pragma unroll
                for (int ct = 0; ct < 4; ++ct) {
                    sa[ct][0] *= scale; sa[ct][1] *= scale;
                    sa[ct][2] *= scale; sa[ct][3] *= scale;
                    cm0 = fmaxf(cm0, fmaxf(sa[ct][0], sa[ct][1]));
                    cm1 = fmaxf(cm1, fmaxf(sa[ct][2], sa[ct][3]));
                }
            } else {
                #pragma unroll
                for (int ct = 0; ct < 4; ++ct) {
                    int c0 = ch * 32 + ct * 8 + 2 * tq;
                    bool v0 = c0 < l, v1 = (c0 + 1) < l;
                    sa[ct][0] = v0 ? sa[ct][0] * scale : -1e30f;
                    sa[ct][1] = v1 ? sa[ct][1] * scale : -1e30f;
                    sa[ct][2] = v0 ? sa[ct][2] * scale : -1e30f;
                    sa[ct][3] = v1 ? sa[ct][3] * scale : -1e30f;
                    cm0 = fmaxf(cm0, fmaxf(sa[ct][0], sa[ct][1]));
                    cm1 = fmaxf(cm1, fmaxf(sa[ct][2], sa[ct][3]));
                }
            }
            cm0 = fmaxf(cm0, __shfl_xor_sync(0xffffffffu, cm0, 1));
            cm0 = fmaxf(cm0, __shfl_xor_sync(0xffffffffu, cm0, 2));
            cm1 = fmaxf(cm1, __shfl_xor_sync(0xffffffffu, cm1, 1));
            cm1 = fmaxf(cm1, __shfl_xor_sync(0xffffffffu, cm1, 2));

            float nm0 = fmaxf(m0, cm0);
            float nm1 = fmaxf(m1, cm1);
            float al0 = __expf(m0 - nm0);
            float al1 = __expf(m1 - nm1);
            m0 = nm0; m1 = nm1;
            sum0 *= al0; sum1 *= al1;
            #pragma unroll
            for (int nt = 0; nt < 4; ++nt) {
                ca[nt][0] *= al0; ca[nt][1] *= al0;
                ca[nt][2] *= al1; ca[nt][3] *= al1;
            }

            if (full) {
                #pragma unroll
                for (int ct = 0; ct < 4; ++ct) {
                    float e0 = __expf(sa[ct][0] - m0);
                    float e1 = __expf(sa[ct][1] - m0);
                    float e2 = __expf(sa[ct][2] - m1);
                    float e3 = __expf(sa[ct][3] - m1);
                    sa[ct][0] = e0; sa[ct][1] = e1; sa[ct][2] = e2; sa[ct][3] = e3;
                    sum0 += e0 + e1; sum1 += e2 + e3;
                }
            } else {
                #pragma unroll
                for (int ct = 0; ct < 4; ++ct) {
                    int c0 = ch * 32 + ct * 8 + 2 * tq;
                    float e0 = (c0 < l)     ? __expf(sa[ct][0] - m0) : 0.f;
                    float e1 = (c0 + 1 < l) ? __expf(sa[ct][1] - m0) : 0.f;
                    float e2 = (c0 < l)     ? __expf(sa[ct][2] - m1) : 0.f;
                    float e3 = (c0 + 1 < l) ? __expf(sa[ct][3] - m1) : 0.f;
                    sa[ct][0] = e0; sa[ct][1] = e1; sa[ct][2] = e2; sa[ct][3] = e3;
                    sum0 += e0 + e1; sum1 += e2 + e3;
                }
            }

            #pragma unroll
            for (int kk2 = 0; kk2 < 2; ++kk2) {
                unsigned pah[4], pal[4];
                bsplit2(sa[2*kk2][0],   sa[2*kk2][1],   pah[0], pal[0]);
                bsplit2(sa[2*kk2][2],   sa[2*kk2][3],   pah[1], pal[1]);
                bsplit2(sa[2*kk2+1][0], sa[2*kk2+1][1], pah[2], pal[2]);
                bsplit2(sa[2*kk2+1][2], sa[2*kk2+1][3], pah[3], pal[3]);
                #pragma unroll
                for (int nt = 0; nt < 4; ++nt) {
                    int base = (nt * 8 + g) * VS + (ch * 2 + kk2) * 8 + tq;
                    unsigned bh0 = Vh[base], bh1 = Vh[base + 4];
                    unsigned bl0 = Vl[base], bl1 = Vl[base + 4];
                    MMA_BF16(ca[nt][0], ca[nt][1], ca[nt][2], ca[nt][3],
                             pah[0], pah[1], pah[2], pah[3], bh0, bh1);
                    MMA_BF16(ca[nt][0], ca[nt][1], ca[nt][2], ca[nt][3],
                             pah[0], pah[1], pah[2], pah[3], bl0, bl1);
                    MMA_BF16(ca[nt][0], ca[nt][1], ca[nt][2], ca[nt][3],
                             pal[0], pal[1], pal[2], pal[3], bh0, bh1);
                }
            }
        }

        sum0 += __shfl_xor_sync(0xffffffffu, sum0, 1);
        sum0 += __shfl_xor_sync(0xffffffffu, sum0, 2);
        sum1 += __shfl_xor_sync(0xffffffffu, sum1, 1);
        sum1 += __shfl_xor_sync(0xffffffffu, sum1, 2);

        float inv0 = 1.f / sum0;
        float inv1 = 1.f / sum1;
        int r0 = i0 + g, r1 = i0 + 8 + g;
        #pragma unroll
        for (int nt = 0; nt < 4; ++nt) {
            int dcol = nt * 8 + 2 * tq;
            if (r0 < l)
                *(float2*)(ctx + (size_t)(n0 + r0) * 128 + hc + dcol) =
                    make_float2(ca[nt][0] * inv0, ca[nt][1] * inv0);
            if (r1 < l)
                *(float2*)(ctx + (size_t)(n0 + r1) * 128 + hc + dcol) =
                    make_float2(ca[nt][2] * inv1, ca[nt][3] * inv1);
        }
    }
}

// ---------------------------------------------------------------------------
extern "C" void kernel_launch(void* const* d_in, const int* in_sizes, int n_in,
                              void* d_out, int out_size)
{
    const float* POI    = (const float*)d_in[0];
    const float* dde    = (const float*)d_in[1];
    const float* attW   = (const float*)d_in[2];
    const float* a_src  = (const float*)d_in[3];
    const float* a_dst  = (const float*)d_in[4];
    const float* in_w   = (const float*)d_in[5];
    const float* in_b   = (const float*)d_in[6];
    const float* out_w  = (const float*)d_in[7];
    const float* out_b  = (const float*)d_in[8];
    const float* ln1g   = (const float*)d_in[9];
    const float* ln1b   = (const float*)d_in[10];
    const float* ln2g   = (const float*)d_in[11];
    const float* ln2b   = (const float*)d_in[12];
    const float* fw1    = (const float*)d_in[13];
    const float* fb1    = (const float*)d_in[14];
    const float* fw2    = (const float*)d_in[15];
    const float* fb2    = (const float*)d_in[16];
    const int* sess_idx  = (const int*)d_in[17];
    const int* edge_dist = (const int*)d_in[18];
    const int* batch_ids = (const int*)d_in[20];
    const int* node_pos  = (const int*)d_in[21];
    const int* lengths   = (const int*)d_in[22];
    int N = in_sizes[17];
    int B = in_sizes[22];
    float* outp = (float*)d_out;

    float *b0, *b1, *b2, *b3, *b4;
    unsigned *wh, *wl;
    cudaGetSymbolAddress((void**)&b0, g_buf0);
    cudaGetSymbolAddress((void**)&b1, g_buf1);
    cudaGetSymbolAddress((void**)&b2, g_buf2);
    cudaGetSymbolAddress((void**)&b3, g_buf3);
    cudaGetSymbolAddress((void**)&b4, g_buf4);
    cudaGetSymbolAddress((void**)&wh, d_wh);
    cudaGetSymbolAddress((void**)&wl, d_wl);

    const int g64_smem  = (2 * APC + 2 * WPC) * (int)sizeof(unsigned);           // ~102 KB
    const int attn_smem = (2 * 160 * QS + 2 * 32 * VS) * (int)sizeof(unsigned);  // ~47.1 KB
    cudaFuncSetAttribute(qkv_kernel,      cudaFuncAttributeMaxDynamicSharedMemorySize, g64_smem);
    cudaFuncSetAttribute(tail1_kernel,    cudaFuncAttributeMaxDynamicSharedMemorySize, g64_smem);
    cudaFuncSetAttribute(tail2_kernel,    cudaFuncAttributeMaxDynamicSharedMemorySize, g64_smem);
    cudaFuncSetAttribute(attn_mma_kernel, cudaFuncAttributeMaxDynamicSharedMemorySize, attn_smem);

    head_kernel<<<16, 1024>>>(lengths, B, attW, a_src, a_dst,
                              in_w, out_w, fw1, fw2, outp, out_size);

    gcn_kernel<<<(N + 7) / 8, 256>>>(POI, dde, sess_idx, edge_dist,
                                     batch_ids, node_pos, lengths,
                                     ln1g, ln1b, N);

    int t64 = (N + 63) / 64;
    dim3 qg(t64, 3);
    qkv_kernel<<<qg, 256, g64_smem>>>(b0, b1, wh, wl, in_b, b2, b3, b4, N);

    dim3 ag(B, 4);
    attn_mma_kernel<<<ag, 256, attn_smem>>>(b2, b3, b4, b0, lengths);

    // out2 -> b3 (k no longer needed)
    tail1_kernel<<<t64, 256, g64_smem>>>(b0, b1, wh + 3 * WPC, wl + 3 * WPC,
                                         out_b, ln2g, ln2b, b3, N);
    tail2_kernel<<<t64, 256, g64_smem>>>(b3, wh + 4 * WPC, wl + 4 * WPC,
                                         fb1, fb2, batch_ids, lengths, outp, N);
}